// round 6
// baseline (speedup 1.0000x reference)
#include <cuda_runtime.h>
#include <math.h>

#define B_  16
#define D_  512
#define T_  2048
#define K_  8
#define C_  1024
#define CH_ 64
#define NQ  (B_*D_*T_)   // 16777216 quantized elements
#define TT  128          // t tile
#define TC  128          // c chunk
#define NBLK (B_*K_*(T_/TT))   // 2048 argmin blocks

// ---------------- scratch (device globals; no allocation allowed) -----------
__device__ int   g_counts[K_*C_];
__device__ float g_cnorm[K_*C_];
__device__ float g_cbT[K_*CH_*C_];          // codebooks transposed to [k][ch][c]
__device__ float g_loss_partial[NBLK];      // one partial per argmin block

// ---------------- packed f32x2 helpers --------------------------------------
__device__ __forceinline__ unsigned long long pack2(float x) {
    unsigned long long r; unsigned int u = __float_as_uint(x);
    asm("mov.b64 %0, {%1, %2};" : "=l"(r) : "r"(u), "r"(u));
    return r;
}
__device__ __forceinline__ unsigned long long fma2(unsigned long long a,
                                                   unsigned long long b,
                                                   unsigned long long c) {
    unsigned long long d;
    asm("fma.rn.f32x2 %0, %1, %2, %3;" : "=l"(d) : "l"(a), "l"(b), "l"(c));
    return d;
}
__device__ __forceinline__ float2 unpack2(unsigned long long v) {
    unsigned int lo, hi;
    asm("mov.b64 {%0, %1}, %2;" : "=r"(lo), "=r"(hi) : "l"(v));
    float2 f; f.x = __uint_as_float(lo); f.y = __uint_as_float(hi);
    return f;
}
// forced separate fp32 add (replicate reference rounding sequence exactly)
__device__ __forceinline__ float fadd_rn(float a, float b) {
    float r; asm("add.f32 %0, %1, %2;" : "=f"(r) : "f"(a), "f"(b)); return r;
}
// cp.async 16B gmem->smem
__device__ __forceinline__ void cp16(void* smem_dst, const void* gmem_src) {
    unsigned s = (unsigned)__cvta_generic_to_shared(smem_dst);
    asm volatile("cp.async.cg.shared.global [%0], [%1], 16;\n"
                 :: "r"(s), "l"(gmem_src) : "memory");
}
__device__ __forceinline__ void cp_commit() {
    asm volatile("cp.async.commit_group;\n" ::: "memory");
}
__device__ __forceinline__ void cp_wait_all() {
    asm volatile("cp.async.wait_group 0;\n" ::: "memory");
}

// ---------------- setup: zero counts, c-norms, codebook transpose -----------
__global__ void setup_kernel(const float* __restrict__ cb) {
    int tid = blockIdx.x * blockDim.x + threadIdx.x;   // 0..8191 (k*1024+c)
    if (tid >= K_*C_) return;
    g_counts[tid] = 0;
    int k = tid >> 10;
    int c = tid & 1023;
    const float* row = cb + (size_t)tid * CH_;
    float s = 0.f;
#pragma unroll
    for (int ch = 0; ch < CH_; ++ch) {
        float v = row[ch];
        s = fmaf(v, v, s);
        g_cbT[((k*CH_ + ch) << 10) + c] = v;   // coalesced write along c
    }
    g_cnorm[tid] = s;
}

// ---------------- fused distance + argmin + gather + write kernel -----------
// grid: (T/TT=16, K=8, B=16), block 256 threads, dyn smem = 96KB
// smem: sX [64][128] (32KB) | sC0 [64][128] (32KB) | sC1 [64][128] (32KB)
__global__ __launch_bounds__(256, 2)
void argmin_kernel(const float* __restrict__ x,
                   const float* __restrict__ cb,
                   float* __restrict__ out) {
    extern __shared__ float smem[];
    float* sX  = smem;                  // [64][TT]
    float* sC0 = smem + 64*TT;          // ping
    float* sC1 = smem + 64*TT + 64*TC;  // pong

    const int tid = threadIdx.x;
    const int b = blockIdx.z, k = blockIdx.y;
    const int t0 = blockIdx.x * TT;
    const int ty = tid >> 4, tx = tid & 15;
    const float* cbb = g_cbT + (size_t)(k*CH_) * C_;

    // load x tile [ch][t] — [ch][t]-major in gmem, coalesced float4
    {
        const float* xb = x + ((size_t)(b*D_ + k*CH_)) * T_ + t0;
#pragma unroll
        for (int j = 0; j < 8; ++j) {
            int idx = tid + 256*j;
            int ch = idx >> 5, c4 = (idx & 31) << 2;
            float4 v = *reinterpret_cast<const float4*>(xb + (size_t)ch * T_ + c4);
            *reinterpret_cast<float4*>(&sX[ch*TT + c4]) = v;
        }
    }
    // prefetch codebook chunk 0 into sC0 (overlaps with xn compute)
#pragma unroll
    for (int j = 0; j < 8; ++j) {
        int idx = tid + 256*j;
        int ch = idx >> 5, c4 = (idx & 31) << 2;
        cp16(&sC0[ch*TC + c4], cbb + (size_t)ch * C_ + c4);
    }
    cp_commit();
    __syncthreads();   // sX visible

    // per-thread x-norms for its 8 t rows (fp32, sequential over ch like ref)
    float xn[8];
#pragma unroll
    for (int i = 0; i < 8; ++i) {
        float s = 0.f;
        const float* col = &sX[ty*8 + i];
#pragma unroll
        for (int ch = 0; ch < 64; ++ch) {
            float v = col[ch*TT];
            s = fmaf(v, v, s);
        }
        xn[i] = s;
    }

    float bestv[8];
    int   bestc[8];
#pragma unroll
    for (int i = 0; i < 8; ++i) { bestv[i] = 3.4e38f; bestc[i] = 0; }

    cp_wait_all();
    __syncthreads();   // chunk 0 visible

#pragma unroll 1
    for (int ci = 0; ci < C_/TC; ++ci) {
        const int cbase = ci * TC;
        float* cur = (ci & 1) ? sC1 : sC0;
        float* nxt = (ci & 1) ? sC0 : sC1;

        // prefetch next chunk while computing this one
        if (ci < C_/TC - 1) {
            const float* g = cbb + cbase + TC;
#pragma unroll
            for (int j = 0; j < 8; ++j) {
                int idx = tid + 256*j;
                int ch = idx >> 5, c4 = (idx & 31) << 2;
                cp16(&nxt[ch*TC + c4], g + (size_t)ch * C_ + c4);
            }
            cp_commit();
        }

        unsigned long long acc[32];
#pragma unroll
        for (int i = 0; i < 32; ++i) acc[i] = 0ull;   // (0.f,0.f)

#pragma unroll 8
        for (int ch = 0; ch < 64; ++ch) {
            const float4 a0 = *reinterpret_cast<const float4*>(&sX[ch*TT + ty*8]);
            const float4 a1 = *reinterpret_cast<const float4*>(&sX[ch*TT + ty*8 + 4]);
            const ulonglong2 b0 = *reinterpret_cast<const ulonglong2*>(&cur[ch*TC + tx*8]);
            const ulonglong2 b1 = *reinterpret_cast<const ulonglong2*>(&cur[ch*TC + tx*8 + 4]);
            unsigned long long ap[8];
            ap[0] = pack2(a0.x); ap[1] = pack2(a0.y); ap[2] = pack2(a0.z); ap[3] = pack2(a0.w);
            ap[4] = pack2(a1.x); ap[5] = pack2(a1.y); ap[6] = pack2(a1.z); ap[7] = pack2(a1.w);
            unsigned long long bp[4]; bp[0] = b0.x; bp[1] = b0.y; bp[2] = b1.x; bp[3] = b1.y;
#pragma unroll
            for (int i = 0; i < 8; ++i)
#pragma unroll
                for (int j = 0; j < 4; ++j)
                    acc[i*4 + j] = fma2(ap[i], bp[j], acc[i*4 + j]);
        }

        // distance exactly like reference: d = fl(fl(xn + cn) + (-2*dot))
        float cn[8];
#pragma unroll
        for (int j = 0; j < 8; ++j) cn[j] = g_cnorm[k*C_ + cbase + tx*8 + j];
#pragma unroll
        for (int i = 0; i < 8; ++i) {
#pragma unroll
            for (int j = 0; j < 4; ++j) {
                float2 dd = unpack2(acc[i*4 + j]);
                float s0 = fadd_rn(xn[i], cn[2*j]);
                float s1 = fadd_rn(xn[i], cn[2*j + 1]);
                float d0 = fadd_rn(s0, -2.f * dd.x);
                float d1 = fadd_rn(s1, -2.f * dd.y);
                int c0 = cbase + tx*8 + 2*j;
                if (d0 < bestv[i]) { bestv[i] = d0; bestc[i] = c0; }
                if (d1 < bestv[i]) { bestv[i] = d1; bestc[i] = c0 + 1; }
            }
        }

        if (ci < C_/TC - 1) {
            cp_wait_all();
            __syncthreads();   // next chunk visible, cur free for overwrite next iter
        }
    }

    // cross-thread (over tx) reduction, tie -> lowest c (argmin first-occurrence)
    __syncthreads();
    float* redV = sC0;                          // [128][16] floats  (8 KB)
    int*   redI = (int*)(sC0 + TT*16);          // [128][16] ints    (8 KB)
#pragma unroll
    for (int i = 0; i < 8; ++i) {
        redV[(ty*8 + i)*16 + tx] = bestv[i];
        redI[(ty*8 + i)*16 + tx] = bestc[i];
    }
    __syncthreads();

    int myc = -1;   // winning codeword for threads tid < 128 (thread owns t = t0+tid)
    if (tid < TT) {
        float bv = redV[tid*16];
        int   bc = redI[tid*16];
#pragma unroll
        for (int j = 1; j < 16; ++j) {
            float v = redV[tid*16 + j];
            int   c = redI[tid*16 + j];
            if (v < bv || (v == bv && c < bc)) { bv = v; bc = c; }
        }
        myc = bc;
        atomicAdd(&g_counts[k*C_ + bc], 1);
    }
    __syncthreads();   // reduction reads done; sC0 free for sQ

    // ---- fused epilogue: gather q rows, write quantized, partial MSE ----
    float* sQ = sC0;                      // [64][TT] (32KB)
    float lacc = 0.f;
    if (tid < TT) {
        const float4* qrow = reinterpret_cast<const float4*>(
            cb + ((size_t)(k*C_ + myc)) * CH_);
        float4 q[16];
#pragma unroll
        for (int i = 0; i < 16; ++i) q[i] = qrow[i];   // full 256B row, L2-resident
        const float* qf = reinterpret_cast<const float*>(q);
#pragma unroll
        for (int ch = 0; ch < 64; ++ch) {
            float qv = qf[ch];
            sQ[ch*TT + tid] = qv;                       // conflict-free (t along lanes)
            float d = sX[ch*TT + tid] - qv;
            lacc = fmaf(d, d, lacc);
        }
    }
    __syncthreads();

    // cooperative float4 stores of the 32KB quantized tile
    {
        float* ob = out + ((size_t)(b*D_ + k*CH_)) * T_ + t0;
#pragma unroll
        for (int j = 0; j < 8; ++j) {
            int idx = tid + 256*j;
            int ch = idx >> 5, c4 = (idx & 31) << 2;
            float4 v = *reinterpret_cast<const float4*>(&sQ[ch*TT + c4]);
            *reinterpret_cast<float4*>(ob + (size_t)ch * T_ + c4) = v;
        }
    }

    // deterministic loss reduction
    float* sred = sC1;   // 256 floats
    sred[tid] = lacc;
    __syncthreads();
#pragma unroll
    for (int s = 128; s > 0; s >>= 1) {
        if (tid < s) sred[tid] += sred[tid + s];
        __syncthreads();
    }
    if (tid == 0)
        g_loss_partial[(b*K_ + k)*(T_/TT) + blockIdx.x] = sred[0];
}

// ---------------- finalize: commit loss + perplexity ------------------------
__global__ void finalize_kernel(float* __restrict__ out) {
    const int tid = threadIdx.x;
    __shared__ float sred[256];
    float s = 0.f;
#pragma unroll
    for (int j = 0; j < NBLK/256; ++j) s += g_loss_partial[tid + 256*j];
    sred[tid] = s;
    __syncthreads();
#pragma unroll
    for (int st = 128; st > 0; st >>= 1) {
        if (tid < st) sred[tid] += sred[tid + st];
        __syncthreads();
    }
    if (tid == 0)
        out[NQ] = sred[0] * 1.25f / (float)NQ;   // codebook + 0.25*encoder loss

    // perplexity: one warp per k
    int w = tid >> 5, lane = tid & 31;
    if (w < K_) {
        float h = 0.f;
        for (int c = lane; c < C_; c += 32) {
            float p = (float)g_counts[w*C_ + c] * (1.f / (B_*T_));
            h += -p * logf(p + 1e-8f);
        }
#pragma unroll
        for (int off = 16; off; off >>= 1) h += __shfl_down_sync(0xffffffffu, h, off);
        if (lane == 0) out[NQ + 1 + w] = expf(h);
    }
}

// ---------------- launch ----------------------------------------------------
extern "C" void kernel_launch(void* const* d_in, const int* in_sizes, int n_in,
                              void* d_out, int out_size) {
    const float* x  = (const float*)d_in[0];   // (B, D, T) fp32
    const float* cb = (const float*)d_in[1];   // (K, C, CH) fp32
    float* out = (float*)d_out;

    const int smem_bytes = 64*TT*4 + 2*64*TC*4;   // 96 KB
    cudaFuncSetAttribute(argmin_kernel,
                         cudaFuncAttributeMaxDynamicSharedMemorySize, smem_bytes);

    setup_kernel<<<32, 256>>>(cb);
    argmin_kernel<<<dim3(T_/TT, K_, B_), 256, smem_bytes>>>(x, cb, out);
    finalize_kernel<<<1, 256>>>(out);
}

// round 8
// speedup vs baseline: 1.0859x; 1.0859x over previous
#include <cuda_runtime.h>
#include <math.h>
#include <stdint.h>

#define B_  16
#define D_  512
#define T_  2048
#define K_  8
#define C_  1024
#define CH_ 64
#define NQ  (B_*D_*T_)
#define TT  128
#define NBLK 2048
#define EPS 1e-3f
#define RS  136              // padded smem row stride (floats): banks (8tg+g)%32 distinct
#define TILE (64*RS)         // 8704 floats

// smem float offsets
#define SA_HI 0
#define SA_LO TILE
#define SB    (2*TILE)           // 4 tiles: buf0{hi,lo}, buf1{hi,lo}
#define SCN   (6*TILE)           // 1024
#define SXN   (6*TILE+1024)      // 128
#define SWIN  (6*TILE+1152)      // 128 int
#define SLIST (6*TILE+1280)      // 128 int
#define SCNT  (6*TILE+1408)      // 1 int
#define SRED  (6*TILE+1412)      // 256
#define SXROW (6*TILE+1668)      // 8*64
#define SM_TOT (6*TILE+2180)     // 54404 floats = 217616 B

// ---------------- scratch ----------------------------------------------------
__device__ int   g_counts[K_*C_];
__device__ float g_cnorm[K_*C_];
__device__ float g_cbT [K_*CH_*C_];   // exact,  [k][ch][c]
__device__ float g_cbHT[K_*CH_*C_];   // tf32 hi [k][ch][c]
__device__ float g_cbLT[K_*CH_*C_];   // tf32 lo [k][ch][c]
__device__ float g_loss_partial[NBLK];

// ---------------- helpers ----------------------------------------------------
__device__ __forceinline__ float fadd_rn(float a, float b) {
    float r; asm("add.f32 %0, %1, %2;" : "=f"(r) : "f"(a), "f"(b)); return r;
}
__device__ __forceinline__ float cvt_tf32(float v) {
    unsigned r; asm("cvt.rna.tf32.f32 %0, %1;" : "=r"(r) : "f"(v));
    return __uint_as_float(r);
}
__device__ __forceinline__ void cp16(float* smem_dst, const float* gmem_src) {
    unsigned s = (unsigned)__cvta_generic_to_shared(smem_dst);
    asm volatile("cp.async.cg.shared.global [%0], [%1], 16;" :: "r"(s), "l"(gmem_src) : "memory");
}
#define CP_COMMIT() asm volatile("cp.async.commit_group;" ::: "memory")
#define CP_WAIT0()  asm volatile("cp.async.wait_group 0;" ::: "memory")
#define CP_WAIT1()  asm volatile("cp.async.wait_group 1;" ::: "memory")

#define MMA_TF32(d, a0,a1,a2,a3, b0,b1) \
    asm volatile("mma.sync.aligned.m16n8k8.row.col.f32.tf32.tf32.f32 " \
        "{%0,%1,%2,%3}, {%4,%5,%6,%7}, {%8,%9}, {%0,%1,%2,%3};" \
        : "+f"((d)[0]), "+f"((d)[1]), "+f"((d)[2]), "+f"((d)[3]) \
        : "r"(a0), "r"(a1), "r"(a2), "r"(a3), "r"(b0), "r"(b1))

// quad merge of (m1,c1,m2) across lanes differing in tg bits; tie -> lower c
#define QMERGE(m1, c1, m2, XOR) do {                                  \
    float _o1 = __shfl_xor_sync(0xffffffffu, m1, XOR);                \
    int   _oc = __shfl_xor_sync(0xffffffffu, c1, XOR);                \
    float _o2 = __shfl_xor_sync(0xffffffffu, m2, XOR);                \
    bool _bet = (_o1 < m1) || (_o1 == m1 && _oc < c1);                \
    float _n2 = fminf(fminf(m2, _o2), _bet ? m1 : _o1);               \
    if (_bet) { m1 = _o1; c1 = _oc; }                                 \
    m2 = _n2; } while (0)

// copy one 64x128 chunk (hi+lo) into padded smem tiles via cp.async
__device__ __forceinline__ void pf_chunk(float* dstHi, const float* srcHi,
                                         const float* srcLo, int tid) {
#pragma unroll
    for (int jj = 0; jj < 8; ++jj) {
        int u = tid + 256*jj;                   // 0..2047
        int ch = u >> 5, c4 = (u & 31) << 2;
        cp16(dstHi + ch*RS + c4,        srcHi + (size_t)ch*1024 + c4);
        cp16(dstHi + TILE + ch*RS + c4, srcLo + (size_t)ch*1024 + c4);
    }
}

// ---------------- setup ------------------------------------------------------
__global__ void setup_kernel(const float* __restrict__ cb) {
    int gid = blockIdx.x * 256 + threadIdx.x;
    if (gid < K_*C_) g_counts[gid] = 0;
    int grp = threadIdx.x >> 6, ch = threadIdx.x & 63;
    int r = blockIdx.x * 4 + grp;               // 0..8191 = k*1024+c
    int k = r >> 10, c = r & 1023;
    float v = cb[(size_t)r * 64 + ch];          // coalesced
    float hf = cvt_tf32(v);
    float lf = cvt_tf32(v - hf);
    size_t o = ((size_t)(k*64 + ch) << 10) + c;
    g_cbT[o]  = v;
    g_cbHT[o] = hf;
    g_cbLT[o] = lf;
    if (ch == 0) {                              // exact cnorm, ref order
        const float* rp = cb + (size_t)r * 64;
        float s = 0.f;
        for (int d = 0; d < 64; ++d) s = fmaf(rp[d], rp[d], s);
        g_cnorm[r] = s;
    }
}

// ---------------- mega kernel ------------------------------------------------
__global__ __launch_bounds__(256, 1)
void vq_kernel(const float* __restrict__ x, const float* __restrict__ cb,
               float* __restrict__ out) {
    extern __shared__ __align__(16) float smem[];
    const int tid = threadIdx.x, w = tid >> 5, lane = tid & 31;
    const int g = lane >> 2, tg = lane & 3;
    const int b = blockIdx.z, k = blockIdx.y, t0 = blockIdx.x * TT;
    const int trow = w * 16;

    int* sWin  = (int*)(smem + SWIN);
    int* sList = (int*)(smem + SLIST);
    int* sCnt  = (int*)(smem + SCNT);

    const float* cbh = g_cbHT + ((size_t)(k*CH_)) * 1024;
    const float* cbl = g_cbLT + ((size_t)(k*CH_)) * 1024;

    // prefetch B chunk 0
    pf_chunk(smem + SB, cbh, cbl, tid);
    CP_COMMIT();

    // A build (tf32 hi/lo) + exact xn (tid<128); cn copy (tid>=128)
    if (tid == 0) *sCnt = 0;
    if (tid < 128) {
        const float* xb = x + ((size_t)(b*D_ + k*CH_)) * T_ + t0 + tid;
        float xn = 0.f;
#pragma unroll
        for (int ch = 0; ch < 64; ++ch) {
            float v = xb[(size_t)ch * T_];
            xn = fmaf(v, v, xn);                 // sequential (proven order)
            float hf = cvt_tf32(v);
            smem[SA_HI + ch*RS + tid] = hf;
            smem[SA_LO + ch*RS + tid] = cvt_tf32(v - hf);
        }
        smem[SXN + tid] = xn;
    } else {
        for (int i = tid - 128; i < 1024; i += 128)
            smem[SCN + i] = g_cnorm[k*C_ + i];
    }
    __syncthreads();

    const float xnl = smem[SXN + trow + g];
    const float xnh = smem[SXN + trow + 8 + g];
    float m1l = 3.4e38f, m2l = 3.4e38f, m1h = 3.4e38f, m2h = 3.4e38f;
    int   c1l = 0, c1h = 0;

#pragma unroll 1
    for (int i = 0; i < 8; ++i) {
        const int j = i & 1;
        if (i < 7) {
            pf_chunk(smem + SB + (j^1)*2*TILE, cbh + (i+1)*128, cbl + (i+1)*128, tid);
            CP_COMMIT();
            CP_WAIT1();
        } else CP_WAIT0();
        __syncthreads();                          // chunk i visible everywhere

        const float* bh = smem + SB + j*2*TILE;
        const float* bl = bh + TILE;
        float acc[64];
#pragma unroll
        for (int q = 0; q < 64; ++q) acc[q] = 0.f;

#pragma unroll
        for (int k0 = 0; k0 < 64; k0 += 8) {
            const float* arh = smem + SA_HI + (k0+tg)*RS + trow + g;
            const float* arl = smem + SA_LO + (k0+tg)*RS + trow + g;
            unsigned a0 = __float_as_uint(arh[0]),    a1 = __float_as_uint(arh[8]);
            unsigned a2 = __float_as_uint(arh[4*RS]), a3 = __float_as_uint(arh[4*RS+8]);
            unsigned l0 = __float_as_uint(arl[0]),    l1 = __float_as_uint(arl[8]);
            unsigned l2 = __float_as_uint(arl[4*RS]), l3 = __float_as_uint(arl[4*RS+8]);
            const float* brh = bh + (k0+tg)*RS + g;
            const float* brl = bl + (k0+tg)*RS + g;
#pragma unroll
            for (int nt = 0; nt < 16; ++nt) {
                unsigned b0 = __float_as_uint(brh[nt*8]);
                unsigned b1 = __float_as_uint(brh[4*RS + nt*8]);
                float* dd = acc + nt*4;
                MMA_TF32(dd, a0,a1,a2,a3, b0,b1);
                MMA_TF32(dd, l0,l1,l2,l3, b0,b1);
                unsigned q0 = __float_as_uint(brl[nt*8]);
                unsigned q1 = __float_as_uint(brl[4*RS + nt*8]);
                MMA_TF32(dd, a0,a1,a2,a3, q0,q1);
            }
        }
        // eval 16 tiles: candidate cols 2tg,2tg+1 per tile, rows g and g+8
#pragma unroll
        for (int nt = 0; nt < 16; ++nt) {
            int c0 = i*128 + nt*8 + 2*tg;
            float cn0 = smem[SCN + c0], cn1 = smem[SCN + c0 + 1];
            float d;
            d = fadd_rn(fadd_rn(xnl, cn0), -2.f*acc[nt*4+0]);
            if (d < m1l) { m2l = m1l; m1l = d; c1l = c0; } else if (d < m2l) m2l = d;
            d = fadd_rn(fadd_rn(xnl, cn1), -2.f*acc[nt*4+1]);
            if (d < m1l) { m2l = m1l; m1l = d; c1l = c0+1; } else if (d < m2l) m2l = d;
            d = fadd_rn(fadd_rn(xnh, cn0), -2.f*acc[nt*4+2]);
            if (d < m1h) { m2h = m1h; m1h = d; c1h = c0; } else if (d < m2h) m2h = d;
            d = fadd_rn(fadd_rn(xnh, cn1), -2.f*acc[nt*4+3]);
            if (d < m1h) { m2h = m1h; m1h = d; c1h = c0+1; } else if (d < m2h) m2h = d;
        }
        __syncthreads();                          // all reads of buf j done
    }

    // quad merge over tg (lanes g*4+tg): xor 1, xor 2 stay inside the quad
    QMERGE(m1l, c1l, m2l, 1); QMERGE(m1l, c1l, m2l, 2);
    QMERGE(m1h, c1h, m2h, 1); QMERGE(m1h, c1h, m2h, 2);
    if (tg == 0) {
        int tl = trow + g, th = trow + 8 + g;
        sWin[tl] = c1l; sWin[th] = c1h;
        if (m2l - m1l < EPS) { int p = atomicAdd(sCnt, 1); sList[p] = tl; }
        if (m2h - m1h < EPS) { int p = atomicAdd(sCnt, 1); sList[p] = th; }
    }
    __syncthreads();

    // ---- warp-parallel exact rescue (bit-proven R2 comparator) ----
    const int nR = *sCnt;
    for (int base = 0; base < nR; base += 8) {
        int li = base + w;
        if (li < nR) {
            int tt = sList[li];
            float* xr = smem + SXROW + w*64;
            xr[lane]      = x[((size_t)(b*D_ + k*CH_ + lane))      * T_ + t0 + tt];
            xr[lane + 32] = x[((size_t)(b*D_ + k*CH_ + lane + 32)) * T_ + t0 + tt];
            __syncwarp();
            float dots[32];
#pragma unroll
            for (int q = 0; q < 32; ++q) dots[q] = 0.f;
            const float* cpk = g_cbT + ((size_t)(k*CH_)) * 1024 + lane;
#pragma unroll 4
            for (int ch = 0; ch < 64; ++ch) {
                float xv = xr[ch];
                const float* pr = cpk + (size_t)ch * 1024;
#pragma unroll
                for (int q = 0; q < 32; ++q)
                    dots[q] = fmaf(xv, pr[q*32], dots[q]);   // coalesced LDG
            }
            float xnt = smem[SXN + tt];
            float bv = 3.4e38f; int bc = 0;
#pragma unroll
            for (int q = 0; q < 32; ++q) {
                int c = lane + 32*q;
                float d = fadd_rn(fadd_rn(xnt, g_cnorm[k*C_ + c]), -2.f*dots[q]);
                if (d < bv) { bv = d; bc = c; }
            }
#pragma unroll
            for (int off = 16; off; off >>= 1) {
                float ov = __shfl_xor_sync(0xffffffffu, bv, off);
                int   oc = __shfl_xor_sync(0xffffffffu, bc, off);
                if (ov < bv || (ov == bv && oc < bc)) { bv = ov; bc = oc; }
            }
            if (lane == 0) sWin[tt] = bc;
        }
    }
    __syncthreads();

    if (tid < 128) atomicAdd(&g_counts[k*C_ + sWin[tid]], 1);

    // ---- epilogue: gather q, write quantized, MSE partial ----
    float* sQ = smem + SB;                        // [64][128]
    float lacc = 0.f;
    if (tid < 128) {
        const int myc = sWin[tid];
        const float4* qrow = (const float4*)(cb + ((size_t)(k*C_ + myc)) * CH_);
        float4 qv4[16];
#pragma unroll
        for (int i = 0; i < 16; ++i) qv4[i] = qrow[i];
        const float* qf = (const float*)qv4;
#pragma unroll
        for (int ch = 0; ch < 64; ++ch) {
            float qv = qf[ch];
            sQ[ch*TT + tid] = qv;
            float xv = smem[SA_HI + ch*RS + tid] + smem[SA_LO + ch*RS + tid];
            float dd = xv - qv;
            lacc = fmaf(dd, dd, lacc);
        }
    }
    __syncthreads();
    {
        float* ob = out + ((size_t)(b*D_ + k*CH_)) * T_ + t0;
#pragma unroll
        for (int jj = 0; jj < 8; ++jj) {
            int u = tid + 256*jj;
            int ch = u >> 5, c4 = (u & 31) << 2;
            float4 v = *reinterpret_cast<const float4*>(&sQ[ch*TT + c4]);
            *reinterpret_cast<float4*>(ob + (size_t)ch * T_ + c4) = v;
        }
    }
    smem[SRED + tid] = lacc;
    __syncthreads();
    for (int s = 128; s > 0; s >>= 1) {
        if (tid < s) smem[SRED + tid] += smem[SRED + tid + s];
        __syncthreads();
    }
    if (tid == 0)
        g_loss_partial[(b*K_ + k)*(T_/TT) + blockIdx.x] = smem[SRED];
}

// ---------------- finalize ---------------------------------------------------
__global__ void finalize_kernel(float* __restrict__ out) {
    const int tid = threadIdx.x;
    __shared__ float sred[256];
    float s = 0.f;
#pragma unroll
    for (int j = 0; j < NBLK/256; ++j) s += g_loss_partial[tid + 256*j];
    sred[tid] = s;
    __syncthreads();
#pragma unroll
    for (int st = 128; st > 0; st >>= 1) {
        if (tid < st) sred[tid] += sred[tid + st];
        __syncthreads();
    }
    if (tid == 0)
        out[NQ] = sred[0] * 1.25f / (float)NQ;

    int w = tid >> 5, lane = tid & 31;
    if (w < K_) {
        float h = 0.f;
        for (int c = lane; c < C_; c += 32) {
            float p = (float)g_counts[w*C_ + c] * (1.f / (B_*T_));
            h += -p * logf(p + 1e-8f);
        }
#pragma unroll
        for (int off = 16; off; off >>= 1) h += __shfl_down_sync(0xffffffffu, h, off);
        if (lane == 0) out[NQ + 1 + w] = expf(h);
    }
}

// ---------------- launch -----------------------------------------------------
extern "C" void kernel_launch(void* const* d_in, const int* in_sizes, int n_in,
                              void* d_out, int out_size) {
    const float* x  = (const float*)d_in[0];
    const float* cb = (const float*)d_in[1];
    float* out = (float*)d_out;

    cudaFuncSetAttribute(vq_kernel,
                         cudaFuncAttributeMaxDynamicSharedMemorySize, SM_TOT * 4);

    setup_kernel<<<2048, 256>>>(cb);
    vq_kernel<<<dim3(T_/TT, K_, B_), 256, SM_TOT * 4>>>(x, cb, out);
    finalize_kernel<<<1, 256>>>(out);
}

// round 9
// speedup vs baseline: 1.6464x; 1.5162x over previous
#include <cuda_runtime.h>
#include <cuda_fp16.h>
#include <math.h>
#include <stdint.h>

#define B_  16
#define D_  512
#define T_  2048
#define K_  8
#define C_  1024
#define CH_ 64
#define NQ  (B_*D_*T_)
#define TT  128
#define NBLK 2048
#define EPS 1e-3f
#define RSH 72                  // padded half row stride

// smem byte offsets
#define ABH   0                 // A hi: 128 rows x 72 halfs = 18432 B
#define ABL   18432
#define BBUF  36864             // 2 bufs x (hi+lo) x 18432 = 73728 B
#define BCN   110592            // float[1024]
#define BXN   114688            // float[128]
#define BWIN  115200            // int[128]
#define BLIST 115712            // int[128]
#define BCNT  116224            // int
#define BRED  116228            // float[256]
#define BXROW 117252            // float[512]
#define SMEM_BYTES 119424

// ---------------- scratch ----------------------------------------------------
__device__ int    g_counts[K_*C_];
__device__ float  g_cnorm[K_*C_];
__device__ float  g_cbT[K_*CH_*C_];     // exact, [k][ch][c] (rescue path)
__device__ __half g_cbHh[K_*C_*CH_];    // fp16 hi, [k][c][ch]
__device__ __half g_cbLh[K_*C_*CH_];    // fp16 lo
__device__ float  g_loss_partial[NBLK];

// ---------------- helpers ----------------------------------------------------
__device__ __forceinline__ float fadd_rn(float a, float b) {
    float r; asm("add.f32 %0, %1, %2;" : "=f"(r) : "f"(a), "f"(b)); return r;
}
__device__ __forceinline__ void cp16(void* smem_dst, const void* gmem_src) {
    unsigned s = (unsigned)__cvta_generic_to_shared(smem_dst);
    asm volatile("cp.async.cg.shared.global [%0], [%1], 16;" :: "r"(s), "l"(gmem_src) : "memory");
}
#define CP_COMMIT() asm volatile("cp.async.commit_group;" ::: "memory")
#define CP_WAIT0()  asm volatile("cp.async.wait_group 0;" ::: "memory")
#define CP_WAIT1()  asm volatile("cp.async.wait_group 1;" ::: "memory")

#define MMA_F16(d, a0,a1,a2,a3, b0,b1) \
    asm volatile("mma.sync.aligned.m16n8k16.row.col.f32.f16.f16.f32 " \
        "{%0,%1,%2,%3}, {%4,%5,%6,%7}, {%8,%9}, {%0,%1,%2,%3};" \
        : "+f"((d)[0]), "+f"((d)[1]), "+f"((d)[2]), "+f"((d)[3]) \
        : "r"(a0), "r"(a1), "r"(a2), "r"(a3), "r"(b0), "r"(b1))

#define QMERGE(m1, c1, m2, XOR) do {                                  \
    float _o1 = __shfl_xor_sync(0xffffffffu, m1, XOR);                \
    int   _oc = __shfl_xor_sync(0xffffffffu, c1, XOR);                \
    float _o2 = __shfl_xor_sync(0xffffffffu, m2, XOR);                \
    bool _bet = (_o1 < m1) || (_o1 == m1 && _oc < c1);                \
    float _n2 = fminf(fminf(m2, _o2), _bet ? m1 : _o1);               \
    if (_bet) { m1 = _o1; c1 = _oc; }                                 \
    m2 = _n2; } while (0)

// prefetch one B chunk (128 codewords, hi+lo) into padded half tiles
__device__ __forceinline__ void pf_chunk(char* dst, const __half* srcHi,
                                         const __half* srcLo, int tid) {
#pragma unroll
    for (int jj = 0; jj < 8; ++jj) {
        int u = tid + 256*jj;                 // 0..2047
        int mat = u >> 10;                    // 0=hi, 1=lo
        int row = (u >> 3) & 127, seg = u & 7;
        const __half* src = (mat ? srcLo : srcHi) + (size_t)row*64 + seg*8;
        cp16(dst + mat*18432 + row*(RSH*2) + seg*16, src);
    }
}

// ---------------- setup ------------------------------------------------------
__global__ void setup_kernel(const float* __restrict__ cb) {
    int gid = blockIdx.x * 256 + threadIdx.x;
    if (gid < K_*C_) g_counts[gid] = 0;
    int grp = threadIdx.x >> 6, ch = threadIdx.x & 63;
    int r = blockIdx.x * 4 + grp;             // 0..8191 = k*1024+c
    int k = r >> 10, c = r & 1023;
    float v = cb[(size_t)r * 64 + ch];        // coalesced
    __half hh = __float2half_rn(v);
    __half hl = __float2half_rn(v - __half2float(hh));
    g_cbHh[(size_t)r * 64 + ch] = hh;
    g_cbLh[(size_t)r * 64 + ch] = hl;
    g_cbT[((size_t)(k*64 + ch) << 10) + c] = v;
    if (ch == 0) {                            // exact cnorm, ref order
        const float* rp = cb + (size_t)r * 64;
        float s = 0.f;
        for (int d = 0; d < 64; ++d) s = fmaf(rp[d], rp[d], s);
        g_cnorm[r] = s;
    }
}

// ---------------- mega kernel ------------------------------------------------
__global__ __launch_bounds__(256, 1)
void vq_kernel(const float* __restrict__ x, const float* __restrict__ cb,
               float* __restrict__ out) {
    extern __shared__ __align__(16) char smem[];
    float* smf   = (float*)smem;
    int*   sWin  = (int*)(smem + BWIN);
    int*   sList = (int*)(smem + BLIST);
    int*   sCnt  = (int*)(smem + BCNT);
    float* sCn   = (float*)(smem + BCN);
    float* sXn   = (float*)(smem + BXN);
    float* sRed  = (float*)(smem + BRED);

    const int tid = threadIdx.x, w = tid >> 5, lane = tid & 31;
    const int g = lane >> 2, tg = lane & 3;
    const int b = blockIdx.z, k = blockIdx.y, t0 = blockIdx.x * TT;
    const int trow = w * 16;

    const __half* cbh = g_cbHh + ((size_t)k << 16);   // k*1024*64
    const __half* cbl = g_cbLh + ((size_t)k << 16);

    pf_chunk(smem + BBUF, cbh, cbl, tid);
    CP_COMMIT();

    // A build (fp16 hi/lo, row-major padded) + exact xn; cn copy
    if (tid == 0) *sCnt = 0;
    if (tid < 128) {
        const float* xb = x + ((size_t)(b*D_ + k*CH_)) * T_ + t0 + tid;
        __half* arh = (__half*)(smem + ABH) + tid * RSH;
        __half* arl = (__half*)(smem + ABL) + tid * RSH;
        float xn = 0.f;
#pragma unroll
        for (int ch = 0; ch < 64; ++ch) {
            float v = xb[(size_t)ch * T_];
            xn = fmaf(v, v, xn);               // sequential (proven order)
            __half hh = __float2half_rn(v);
            arh[ch] = hh;
            arl[ch] = __float2half_rn(v - __half2float(hh));
        }
        sXn[tid] = xn;
    } else {
        for (int i = tid - 128; i < 1024; i += 128)
            sCn[i] = g_cnorm[k*C_ + i];
    }
    __syncthreads();

    const float xnl = sXn[trow + g];
    const float xnh = sXn[trow + 8 + g];
    float m1l = 3.4e38f, m2l = 3.4e38f, m1h = 3.4e38f, m2h = 3.4e38f;
    int   c1l = 0, c1h = 0;

    const uint32_t* a32h = (const uint32_t*)(smem + ABH);
    const uint32_t* a32l = (const uint32_t*)(smem + ABL);

#pragma unroll 1
    for (int i = 0; i < 8; ++i) {
        const int j = i & 1;
        if (i < 7) {
            pf_chunk(smem + BBUF + (j^1)*36864,
                     cbh + (size_t)(i+1)*128*64, cbl + (size_t)(i+1)*128*64, tid);
            CP_COMMIT();
            CP_WAIT1();
        } else CP_WAIT0();
        __syncthreads();

        const uint32_t* b32h = (const uint32_t*)(smem + BBUF + j*36864);
        const uint32_t* b32l = (const uint32_t*)(smem + BBUF + j*36864 + 18432);
        float acc[64];
#pragma unroll
        for (int q = 0; q < 64; ++q) acc[q] = 0.f;

#pragma unroll
        for (int k0 = 0; k0 < 4; ++k0) {       // 16 k per step; word off = 8*k0
            const int aw = (trow + g)*(RSH/2) + tg + 8*k0;
            uint32_t a0 = a32h[aw],       a1 = a32h[aw + 8*(RSH/2)];
            uint32_t a2 = a32h[aw + 4],   a3 = a32h[aw + 8*(RSH/2) + 4];
            uint32_t l0 = a32l[aw],       l1 = a32l[aw + 8*(RSH/2)];
            uint32_t l2 = a32l[aw + 4],   l3 = a32l[aw + 8*(RSH/2) + 4];
#pragma unroll
            for (int nt = 0; nt < 16; ++nt) {
                const int bw = (nt*8 + g)*(RSH/2) + tg + 8*k0;
                uint32_t b0 = b32h[bw], b1 = b32h[bw + 4];
                float* dd = acc + nt*4;
                MMA_F16(dd, a0,a1,a2,a3, b0,b1);
                MMA_F16(dd, l0,l1,l2,l3, b0,b1);
                uint32_t q0 = b32l[bw], q1 = b32l[bw + 4];
                MMA_F16(dd, a0,a1,a2,a3, q0,q1);
            }
        }
#pragma unroll
        for (int nt = 0; nt < 16; ++nt) {
            int c0 = i*128 + nt*8 + 2*tg;
            float cn0 = sCn[c0], cn1 = sCn[c0 + 1];
            float d;
            d = fadd_rn(fadd_rn(xnl, cn0), -2.f*acc[nt*4+0]);
            if (d < m1l) { m2l = m1l; m1l = d; c1l = c0; } else if (d < m2l) m2l = d;
            d = fadd_rn(fadd_rn(xnl, cn1), -2.f*acc[nt*4+1]);
            if (d < m1l) { m2l = m1l; m1l = d; c1l = c0+1; } else if (d < m2l) m2l = d;
            d = fadd_rn(fadd_rn(xnh, cn0), -2.f*acc[nt*4+2]);
            if (d < m1h) { m2h = m1h; m1h = d; c1h = c0; } else if (d < m2h) m2h = d;
            d = fadd_rn(fadd_rn(xnh, cn1), -2.f*acc[nt*4+3]);
            if (d < m1h) { m2h = m1h; m1h = d; c1h = c0+1; } else if (d < m2h) m2h = d;
        }
        __syncthreads();
    }

    QMERGE(m1l, c1l, m2l, 1); QMERGE(m1l, c1l, m2l, 2);
    QMERGE(m1h, c1h, m2h, 1); QMERGE(m1h, c1h, m2h, 2);
    if (tg == 0) {
        int tl = trow + g, th = trow + 8 + g;
        sWin[tl] = c1l; sWin[th] = c1h;
        if (m2l - m1l < EPS) { int p = atomicAdd(sCnt, 1); sList[p] = tl; }
        if (m2h - m1h < EPS) { int p = atomicAdd(sCnt, 1); sList[p] = th; }
    }
    __syncthreads();

    // ---- warp-parallel exact rescue (bit-proven R2 comparator) ----
    const int nR = *sCnt;
    for (int base = 0; base < nR; base += 8) {
        int li = base + w;
        if (li < nR) {
            int tt = sList[li];
            float* xr = (float*)(smem + BXROW) + w*64;
            xr[lane]      = x[((size_t)(b*D_ + k*CH_ + lane))      * T_ + t0 + tt];
            xr[lane + 32] = x[((size_t)(b*D_ + k*CH_ + lane + 32)) * T_ + t0 + tt];
            __syncwarp();
            float dots[32];
#pragma unroll
            for (int q = 0; q < 32; ++q) dots[q] = 0.f;
            const float* cpk = g_cbT + ((size_t)(k*CH_) << 10) + lane;
#pragma unroll 4
            for (int ch = 0; ch < 64; ++ch) {
                float xv = xr[ch];
                const float* pr = cpk + ((size_t)ch << 10);
#pragma unroll
                for (int q = 0; q < 32; ++q)
                    dots[q] = fmaf(xv, pr[q*32], dots[q]);
            }
            float xnt = sXn[tt];
            float bv = 3.4e38f; int bc = 0;
#pragma unroll
            for (int q = 0; q < 32; ++q) {
                int c = lane + 32*q;
                float d = fadd_rn(fadd_rn(xnt, g_cnorm[k*C_ + c]), -2.f*dots[q]);
                if (d < bv) { bv = d; bc = c; }
            }
#pragma unroll
            for (int off = 16; off; off >>= 1) {
                float ov = __shfl_xor_sync(0xffffffffu, bv, off);
                int   oc = __shfl_xor_sync(0xffffffffu, bc, off);
                if (ov < bv || (ov == bv && oc < bc)) { bv = ov; bc = oc; }
            }
            if (lane == 0) sWin[tt] = bc;
        }
    }
    __syncthreads();

    if (tid < 128) atomicAdd(&g_counts[k*C_ + sWin[tid]], 1);

    // ---- epilogue: gather q, write quantized, MSE partial ----
    float* sQ = (float*)(smem + BBUF);            // 32KB, B bufs dead now
    float lacc = 0.f;
    if (tid < 128) {
        const int myc = sWin[tid];
        const float4* qrow = (const float4*)(cb + ((size_t)(k*C_ + myc)) * CH_);
        float4 qv4[16];
#pragma unroll
        for (int i = 0; i < 16; ++i) qv4[i] = qrow[i];
        const float* qf = (const float*)qv4;
        const __half* arh = (const __half*)(smem + ABH) + tid * RSH;
        const __half* arl = (const __half*)(smem + ABL) + tid * RSH;
#pragma unroll
        for (int ch = 0; ch < 64; ++ch) {
            float qv = qf[ch];
            sQ[ch*TT + tid] = qv;
            float xv = __half2float(arh[ch]) + __half2float(arl[ch]);
            float dd = xv - qv;
            lacc = fmaf(dd, dd, lacc);
        }
    }
    __syncthreads();
    {
        float* ob = out + ((size_t)(b*D_ + k*CH_)) * T_ + t0;
#pragma unroll
        for (int jj = 0; jj < 8; ++jj) {
            int u = tid + 256*jj;
            int ch = u >> 5, c4 = (u & 31) << 2;
            float4 v = *reinterpret_cast<const float4*>(&sQ[ch*TT + c4]);
            *reinterpret_cast<float4*>(ob + (size_t)ch * T_ + c4) = v;
        }
    }
    sRed[tid] = lacc;
    __syncthreads();
    for (int s = 128; s > 0; s >>= 1) {
        if (tid < s) sRed[tid] += sRed[tid + s];
        __syncthreads();
    }
    if (tid == 0)
        g_loss_partial[(b*K_ + k)*(T_/TT) + blockIdx.x] = sRed[0];
}

// ---------------- finalize ---------------------------------------------------
__global__ void finalize_kernel(float* __restrict__ out) {
    const int tid = threadIdx.x;
    __shared__ float sred[256];
    float s = 0.f;
#pragma unroll
    for (int j = 0; j < NBLK/256; ++j) s += g_loss_partial[tid + 256*j];
    sred[tid] = s;
    __syncthreads();
#pragma unroll
    for (int st = 128; st > 0; st >>= 1) {
        if (tid < st) sred[tid] += sred[tid + st];
        __syncthreads();
    }
    if (tid == 0)
        out[NQ] = sred[0] * 1.25f / (float)NQ;

    int w = tid >> 5, lane = tid & 31;
    if (w < K_) {
        float h = 0.f;
        for (int c = lane; c < C_; c += 32) {
            float p = (float)g_counts[w*C_ + c] * (1.f / (B_*T_));
            h += -p * logf(p + 1e-8f);
        }
#pragma unroll
        for (int off = 16; off; off >>= 1) h += __shfl_down_sync(0xffffffffu, h, off);
        if (lane == 0) out[NQ + 1 + w] = expf(h);
    }
}

// ---------------- launch -----------------------------------------------------
extern "C" void kernel_launch(void* const* d_in, const int* in_sizes, int n_in,
                              void* d_out, int out_size) {
    const float* x  = (const float*)d_in[0];
    const float* cb = (const float*)d_in[1];
    float* out = (float*)d_out;

    cudaFuncSetAttribute(vq_kernel,
                         cudaFuncAttributeMaxDynamicSharedMemorySize, SMEM_BYTES);

    setup_kernel<<<2048, 256>>>(cb);
    vq_kernel<<<dim3(T_/TT, K_, B_), 256, SMEM_BYTES>>>(x, cb, out);
    finalize_kernel<<<1, 256>>>(out);
}

// round 11
// speedup vs baseline: 1.8180x; 1.1043x over previous
#include <cuda_runtime.h>
#include <cuda_fp16.h>
#include <math.h>
#include <stdint.h>

#define B_  16
#define D_  512
#define T_  2048
#define K_  8
#define C_  1024
#define CH_ 64
#define NQ  (B_*D_*T_)
#define TT  128
#define NBLK 2048
#define EPS 1e-2f
#define RSH 72                  // padded half row stride (36 words: banks 4g+tg distinct)

// smem byte offsets
#define ABH   0                 // A hi: 128 x 72 halfs = 18432 B
#define BBUF  18432             // 2 bufs x 18432 (hi only)
#define BCN   55296             // float[1024]
#define BXN   59392             // float[128]
#define BWIN  59904             // int[128]
#define BLIST 60416             // int[128]
#define BCNT  60928             // int (pad to 16)
#define BRED  60944             // float[256]
#define BXROW 61968             // float[8*64]
#define SMEM_BYTES 64016

// ---------------- scratch ----------------------------------------------------
__device__ int    g_counts[K_*C_];
__device__ float  g_cnorm[K_*C_];
__device__ float  g_cbT[K_*CH_*C_];     // exact, [k][ch][c] (rescue path)
__device__ __half g_cbHh[K_*C_*CH_];    // fp16 hi, [k][c][ch]
__device__ float  g_loss_partial[NBLK];

// ---------------- helpers ----------------------------------------------------
__device__ __forceinline__ float fadd_rn(float a, float b) {
    float r; asm("add.f32 %0, %1, %2;" : "=f"(r) : "f"(a), "f"(b)); return r;
}
__device__ __forceinline__ void cp16(void* smem_dst, const void* gmem_src) {
    unsigned s = (unsigned)__cvta_generic_to_shared(smem_dst);
    asm volatile("cp.async.cg.shared.global [%0], [%1], 16;" :: "r"(s), "l"(gmem_src) : "memory");
}
#define CP_COMMIT() asm volatile("cp.async.commit_group;" ::: "memory")
#define CP_WAIT0()  asm volatile("cp.async.wait_group 0;" ::: "memory")
#define CP_WAIT1()  asm volatile("cp.async.wait_group 1;" ::: "memory")

#define MMA_F16(d, a0,a1,a2,a3, b0,b1) \
    asm volatile("mma.sync.aligned.m16n8k16.row.col.f32.f16.f16.f32 " \
        "{%0,%1,%2,%3}, {%4,%5,%6,%7}, {%8,%9}, {%0,%1,%2,%3};" \
        : "+f"((d)[0]), "+f"((d)[1]), "+f"((d)[2]), "+f"((d)[3]) \
        : "r"(a0), "r"(a1), "r"(a2), "r"(a3), "r"(b0), "r"(b1))

#define QMERGE(m1, c1, m2, XOR) do {                                  \
    float _o1 = __shfl_xor_sync(0xffffffffu, m1, XOR);                \
    int   _oc = __shfl_xor_sync(0xffffffffu, c1, XOR);                \
    float _o2 = __shfl_xor_sync(0xffffffffu, m2, XOR);                \
    bool _bet = (_o1 < m1) || (_o1 == m1 && _oc < c1);                \
    float _n2 = fminf(fminf(m2, _o2), _bet ? m1 : _o1);               \
    if (_bet) { m1 = _o1; c1 = _oc; }                                 \
    m2 = _n2; } while (0)

// prefetch one B chunk (128 codewords, hi only) into padded half tile
__device__ __forceinline__ void pf_chunk(char* dst, const __half* srcHi, int tid) {
#pragma unroll
    for (int jj = 0; jj < 4; ++jj) {
        int u = tid + 256*jj;                 // 0..1023
        int row = u >> 3, seg = u & 7;
        cp16(dst + row*(RSH*2) + seg*16, srcHi + (size_t)row*64 + seg*8);
    }
}

// ---------------- setup ------------------------------------------------------
__global__ void setup_kernel(const float* __restrict__ cb) {
    int gid = blockIdx.x * 256 + threadIdx.x;
    if (gid < K_*C_) g_counts[gid] = 0;
    int grp = threadIdx.x >> 6, ch = threadIdx.x & 63;
    int r = blockIdx.x * 4 + grp;             // 0..8191 = k*1024+c
    int k = r >> 10, c = r & 1023;
    float v = cb[(size_t)r * 64 + ch];        // coalesced
    g_cbHh[(size_t)r * 64 + ch] = __float2half_rn(v);
    g_cbT[((size_t)(k*64 + ch) << 10) + c] = v;
    if (ch == 0) {                            // exact cnorm, ref order
        const float* rp = cb + (size_t)r * 64;
        float s = 0.f;
        for (int d = 0; d < 64; ++d) s = fmaf(rp[d], rp[d], s);
        g_cnorm[r] = s;
    }
}

// ---------------- mega kernel ------------------------------------------------
__global__ __launch_bounds__(256, 2)
void vq_kernel(const float* __restrict__ x, const float* __restrict__ cb,
               float* __restrict__ out) {
    extern __shared__ __align__(16) char smem[];
    int*   sWin  = (int*)(smem + BWIN);
    int*   sList = (int*)(smem + BLIST);
    int*   sCnt  = (int*)(smem + BCNT);
    float* sCn   = (float*)(smem + BCN);
    float* sXn   = (float*)(smem + BXN);
    float* sRed  = (float*)(smem + BRED);

    const int tid = threadIdx.x, w = tid >> 5, lane = tid & 31;
    const int g = lane >> 2, tg = lane & 3;
    const int b = blockIdx.z, k = blockIdx.y, t0 = blockIdx.x * TT;
    const int trow = w * 16;

    const __half* cbh = g_cbHh + ((size_t)k << 16);   // k*1024*64

    pf_chunk(smem + BBUF, cbh, tid);
    CP_COMMIT();

    // A build (fp16 hi, row-major padded) + exact xn; cn copy
    if (tid == 0) *sCnt = 0;
    if (tid < 128) {
        const float* xb = x + ((size_t)(b*D_ + k*CH_)) * T_ + t0 + tid;
        __half* arh = (__half*)(smem + ABH) + tid * RSH;
        float xn = 0.f;
#pragma unroll
        for (int ch = 0; ch < 64; ++ch) {
            float v = xb[(size_t)ch * T_];
            xn = fmaf(v, v, xn);               // sequential (proven order)
            arh[ch] = __float2half_rn(v);
        }
        sXn[tid] = xn;
    } else {
        for (int i = tid - 128; i < 1024; i += 128)
            sCn[i] = g_cnorm[k*C_ + i];
    }
    __syncthreads();

    const float xnl = sXn[trow + g];
    const float xnh = sXn[trow + 8 + g];
    float m1l = 3.4e38f, m2l = 3.4e38f, m1h = 3.4e38f, m2h = 3.4e38f;
    int   c1l = 0, c1h = 0;

    const uint32_t* a32h = (const uint32_t*)(smem + ABH);

#pragma unroll 1
    for (int i = 0; i < 8; ++i) {
        const int j = i & 1;
        if (i < 7) {
            pf_chunk(smem + BBUF + (j^1)*18432, cbh + (size_t)(i+1)*128*64, tid);
            CP_COMMIT();
            CP_WAIT1();
        } else CP_WAIT0();
        __syncthreads();

        const uint32_t* b32h = (const uint32_t*)(smem + BBUF + j*18432);
        float acc[64];
#pragma unroll
        for (int q = 0; q < 64; ++q) acc[q] = 0.f;

#pragma unroll
        for (int k0 = 0; k0 < 4; ++k0) {       // 16 k per step
            const int aw = (trow + g)*(RSH/2) + tg + 8*k0;
            uint32_t a0 = a32h[aw],     a1 = a32h[aw + 8*(RSH/2)];
            uint32_t a2 = a32h[aw + 4], a3 = a32h[aw + 8*(RSH/2) + 4];
#pragma unroll
            for (int nt = 0; nt < 16; ++nt) {
                const int bw = (nt*8 + g)*(RSH/2) + tg + 8*k0;
                uint32_t b0 = b32h[bw], b1 = b32h[bw + 4];
                MMA_F16(acc + nt*4, a0,a1,a2,a3, b0,b1);
            }
        }
#pragma unroll
        for (int nt = 0; nt < 16; ++nt) {
            int c0 = i*128 + nt*8 + 2*tg;
            float cn0 = sCn[c0], cn1 = sCn[c0 + 1];
            float d;
            d = fadd_rn(fadd_rn(xnl, cn0), -2.f*acc[nt*4+0]);
            if (d < m1l) { m2l = m1l; m1l = d; c1l = c0; } else if (d < m2l) m2l = d;
            d = fadd_rn(fadd_rn(xnl, cn1), -2.f*acc[nt*4+1]);
            if (d < m1l) { m2l = m1l; m1l = d; c1l = c0+1; } else if (d < m2l) m2l = d;
            d = fadd_rn(fadd_rn(xnh, cn0), -2.f*acc[nt*4+2]);
            if (d < m1h) { m2h = m1h; m1h = d; c1h = c0; } else if (d < m2h) m2h = d;
            d = fadd_rn(fadd_rn(xnh, cn1), -2.f*acc[nt*4+3]);
            if (d < m1h) { m2h = m1h; m1h = d; c1h = c0+1; } else if (d < m2h) m2h = d;
        }
        __syncthreads();
    }

    QMERGE(m1l, c1l, m2l, 1); QMERGE(m1l, c1l, m2l, 2);
    QMERGE(m1h, c1h, m2h, 1); QMERGE(m1h, c1h, m2h, 2);
    if (tg == 0) {
        int tl = trow + g, th = trow + 8 + g;
        sWin[tl] = c1l; sWin[th] = c1h;
        if (m2l - m1l < EPS) { int p = atomicAdd(sCnt, 1); sList[p] = tl; }
        if (m2h - m1h < EPS) { int p = atomicAdd(sCnt, 1); sList[p] = th; }
    }
    __syncthreads();

    // ---- warp-parallel exact rescue (bit-proven R2 comparator) ----
    const int nR = *sCnt;
    for (int base = 0; base < nR; base += 8) {
        int li = base + w;
        if (li < nR) {
            int tt = sList[li];
            float* xr = (float*)(smem + BXROW) + w*64;
            xr[lane]      = x[((size_t)(b*D_ + k*CH_ + lane))      * T_ + t0 + tt];
            xr[lane + 32] = x[((size_t)(b*D_ + k*CH_ + lane + 32)) * T_ + t0 + tt];
            __syncwarp();
            float dots[32];
#pragma unroll
            for (int q = 0; q < 32; ++q) dots[q] = 0.f;
            const float* cpk = g_cbT + ((size_t)(k*CH_) << 10) + lane;
#pragma unroll 4
            for (int ch = 0; ch < 64; ++ch) {
                float xv = xr[ch];
                const float* pr = cpk + ((size_t)ch << 10);
#pragma unroll
                for (int q = 0; q < 32; ++q)
                    dots[q] = fmaf(xv, pr[q*32], dots[q]);
            }
            float xnt = sXn[tt];
            float bv = 3.4e38f; int bc = 0;
#pragma unroll
            for (int q = 0; q < 32; ++q) {
                int c = lane + 32*q;
                float d = fadd_rn(fadd_rn(xnt, g_cnorm[k*C_ + c]), -2.f*dots[q]);
                if (d < bv) { bv = d; bc = c; }
            }
#pragma unroll
            for (int off = 16; off; off >>= 1) {
                float ov = __shfl_xor_sync(0xffffffffu, bv, off);
                int   oc = __shfl_xor_sync(0xffffffffu, bc, off);
                if (ov < bv || (ov == bv && oc < bc)) { bv = ov; bc = oc; }
            }
            if (lane == 0) sWin[tt] = bc;
        }
    }
    __syncthreads();

    if (tid < 128) atomicAdd(&g_counts[k*C_ + sWin[tid]], 1);

    // ---- epilogue: gather q, write quantized, MSE partial ----
    float* sQ = (float*)(smem + BBUF);            // 32KB needed <= 36864 avail
    float lacc = 0.f;
    if (tid < 128) {
        const int myc = sWin[tid];
        const float4* qrow = (const float4*)(cb + ((size_t)(k*C_ + myc)) * CH_);
        float4 qv4[16];
#pragma unroll
        for (int i = 0; i < 16; ++i) qv4[i] = qrow[i];
        const float* qf = (const float*)qv4;
        const __half* arh = (const __half*)(smem + ABH) + tid * RSH;
#pragma unroll
        for (int ch = 0; ch < 64; ++ch) {
            float qv = qf[ch];
            sQ[ch*TT + tid] = qv;
            float dd = __half2float(arh[ch]) - qv;   // x to fp16 (loss err ~1e-7 rel)
            lacc = fmaf(dd, dd, lacc);
        }
    }
    __syncthreads();
    {
        float* ob = out + ((size_t)(b*D_ + k*CH_)) * T_ + t0;
#pragma unroll
        for (int jj = 0; jj < 8; ++jj) {
            int u = tid + 256*jj;
            int ch = u >> 5, c4 = (u & 31) << 2;
            float4 v = *reinterpret_cast<const float4*>(&sQ[ch*TT + c4]);
            *reinterpret_cast<float4*>(ob + (size_t)ch * T_ + c4) = v;
        }
    }
    sRed[tid] = lacc;
    __syncthreads();
    for (int s = 128; s > 0; s >>= 1) {
        if (tid < s) sRed[tid] += sRed[tid + s];
        __syncthreads();
    }
    if (tid == 0)
        g_loss_partial[(b*K_ + k)*(T_/TT) + blockIdx.x] = sRed[0];
}

// ---------------- finalize ---------------------------------------------------
__global__ void finalize_kernel(float* __restrict__ out) {
    const int tid = threadIdx.x;
    __shared__ float sred[256];
    float s = 0.f;
#pragma unroll
    for (int j = 0; j < NBLK/256; ++j) s += g_loss_partial[tid + 256*j];
    sred[tid] = s;
    __syncthreads();
#pragma unroll
    for (int st = 128; st > 0; st >>= 1) {
        if (tid < st) sred[tid] += sred[tid + st];
        __syncthreads();
    }
    if (tid == 0)
        out[NQ] = sred[0] * 1.25f / (float)NQ;

    int w = tid >> 5, lane = tid & 31;
    if (w < K_) {
        float h = 0.f;
        for (int c = lane; c < C_; c += 32) {
            float p = (float)g_counts[w*C_ + c] * (1.f / (B_*T_));
            h += -p * logf(p + 1e-8f);
        }
#pragma unroll
        for (int off = 16; off; off >>= 1) h += __shfl_down_sync(0xffffffffu, h, off);
        if (lane == 0) out[NQ + 1 + w] = expf(h);
    }
}

// ---------------- launch -----------------------------------------------------
extern "C" void kernel_launch(void* const* d_in, const int* in_sizes, int n_in,
                              void* d_out, int out_size) {
    const float* x  = (const float*)d_in[0];
    const float* cb = (const float*)d_in[1];
    float* out = (float*)d_out;

    cudaFuncSetAttribute(vq_kernel,
                         cudaFuncAttributeMaxDynamicSharedMemorySize, SMEM_BYTES);

    setup_kernel<<<2048, 256>>>(cb);
    vq_kernel<<<dim3(T_/TT, K_, B_), 256, SMEM_BYTES>>>(x, cb, out);
    finalize_kernel<<<1, 256>>>(out);
}